// round 3
// baseline (speedup 1.0000x reference)
#include <cuda_runtime.h>
#include <cuda_bf16.h>

// Problem constants
#define Bn 2
#define Sn 2048
#define Dn 1024
#define Hn 16
#define HDn 64
#define Mn (Bn * Sn)          // 4096 rows for the projection GEMMs

// -------- scratch (no allocations allowed; device globals) --------
__device__ float g_q[Bn * Sn * Dn];   // 16 MiB
__device__ float g_k[Bn * Sn * Dn];   // 16 MiB
__device__ float g_v[Bn * Sn * Dn];   // 16 MiB
__device__ float g_o[Bn * Sn * Dn];   // 16 MiB (attention output, pre out-proj)

// ============================================================================
// SGEMM (NT): C[m,n] = sum_k A[m,k] * W[n,k] + bias[n]
// A: [M, K] row-major, W: [N, K] row-major (torch Linear weight), K = Dn.
// 128x128 blocktile, BK=8, 256 threads, 8x8 per-thread microtile.
// Double-buffered smem: compute from buffer p while the prefetched k-tile is
// stored into buffer p^1 -> one __syncthreads per k-step, STS overlaps FFMA.
// All dims are multiples of the tile sizes -> no bounds checks.
// ============================================================================
__device__ __forceinline__ void sgemm_body(const float* __restrict__ A,
                                           const float* __restrict__ W,
                                           const float* __restrict__ bias,
                                           float* __restrict__ C)
{
    const int K = Dn;
    const int N = Dn;

    __shared__ float As[2][8][128];
    __shared__ float Bs[2][8][128];

    const int tid  = threadIdx.x;
    const int cCol = blockIdx.x;   // along N (8 blocks)
    const int cRow = blockIdx.y;   // along M (32 blocks)

    const float* Ab = A + cRow * 128 * K;
    const float* Wb = W + cCol * 128 * K;

    // loaders: each thread loads one float4 of A and one of W per k-step
    const int loadRow = tid >> 1;        // 0..127
    const int loadCol = (tid & 1) * 4;   // 0 or 4

    // compute mapping: 16x16 thread grid, 8x8 microtile
    const int tr = tid >> 4;             // 0..15
    const int tc = tid & 15;             // 0..15

    float acc[8][8];
#pragma unroll
    for (int i = 0; i < 8; i++)
#pragma unroll
        for (int j = 0; j < 8; j++) acc[i][j] = 0.f;

    float regM[8], regN[8];

    const float* Aload = Ab + loadRow * K + loadCol;
    const float* Wload = Wb + loadRow * K + loadCol;

    // prologue: fetch k-tile 0 and stage into buffer 0
    {
        float4 a4 = *(const float4*)(Aload);
        float4 w4 = *(const float4*)(Wload);
        As[0][loadCol + 0][loadRow] = a4.x;
        As[0][loadCol + 1][loadRow] = a4.y;
        As[0][loadCol + 2][loadRow] = a4.z;
        As[0][loadCol + 3][loadRow] = a4.w;
        Bs[0][loadCol + 0][loadRow] = w4.x;
        Bs[0][loadCol + 1][loadRow] = w4.y;
        Bs[0][loadCol + 2][loadRow] = w4.z;
        Bs[0][loadCol + 3][loadRow] = w4.w;
    }
    __syncthreads();

    int p = 0;
    for (int k0 = 0; k0 < K; k0 += 8) {
        // prefetch next k-tile from global into registers
        float4 a4, w4;
        const bool more = (k0 + 8 < K);
        if (more) {
            a4 = *(const float4*)(Aload + k0 + 8);
            w4 = *(const float4*)(Wload + k0 + 8);
        }

        // compute on buffer p
#pragma unroll
        for (int kk = 0; kk < 8; kk++) {
#pragma unroll
            for (int i = 0; i < 8; i++) regM[i] = As[p][kk][tr * 8 + i];
#pragma unroll
            for (int j = 0; j < 8; j++) regN[j] = Bs[p][kk][tc * 8 + j];
#pragma unroll
            for (int i = 0; i < 8; i++)
#pragma unroll
                for (int j = 0; j < 8; j++)
                    acc[i][j] += regM[i] * regN[j];
        }

        // stage prefetched tile into the other buffer (no conflict with reads
        // of buffer p), then one barrier before switching
        if (more) {
            As[p ^ 1][loadCol + 0][loadRow] = a4.x;
            As[p ^ 1][loadCol + 1][loadRow] = a4.y;
            As[p ^ 1][loadCol + 2][loadRow] = a4.z;
            As[p ^ 1][loadCol + 3][loadRow] = a4.w;
            Bs[p ^ 1][loadCol + 0][loadRow] = w4.x;
            Bs[p ^ 1][loadCol + 1][loadRow] = w4.y;
            Bs[p ^ 1][loadCol + 2][loadRow] = w4.z;
            Bs[p ^ 1][loadCol + 3][loadRow] = w4.w;
            __syncthreads();
            p ^= 1;
        }
    }

    // epilogue: add bias, vectorized stores
#pragma unroll
    for (int i = 0; i < 8; i++) {
        const int row = cRow * 128 + tr * 8 + i;
#pragma unroll
        for (int j = 0; j < 8; j += 4) {
            const int col = cCol * 128 + tc * 8 + j;
            float4 v;
            v.x = acc[i][j + 0] + bias[col + 0];
            v.y = acc[i][j + 1] + bias[col + 1];
            v.z = acc[i][j + 2] + bias[col + 2];
            v.w = acc[i][j + 3] + bias[col + 3];
            *(float4*)(C + (size_t)row * N + col) = v;
        }
    }
}

// Fused Q/K/V projection: gridDim.z selects which projection this block does.
__global__ __launch_bounds__(256)
void sgemm_qkv_kernel(const float* __restrict__ x,
                      const float* __restrict__ wq, const float* __restrict__ bq,
                      const float* __restrict__ wk, const float* __restrict__ bk,
                      const float* __restrict__ wv, const float* __restrict__ bv)
{
    const float* W;
    const float* bias;
    float* out;
    if (blockIdx.z == 0)      { W = wq; bias = bq; out = g_q; }
    else if (blockIdx.z == 1) { W = wk; bias = bk; out = g_k; }
    else                      { W = wv; bias = bv; out = g_v; }
    sgemm_body(x, W, bias, out);
}

// Output projection: d_out = g_o @ w_out^T + b_out
__global__ __launch_bounds__(256)
void sgemm_out_kernel(const float* __restrict__ wout,
                      const float* __restrict__ bout,
                      float* __restrict__ out)
{
    sgemm_body(g_o, wout, bout, out);
}

// ============================================================================
// Causal flash attention (fp32).
// grid: (S/128, H, B); block: 128 threads; one thread per query row.
// K/V tiles (64 x 64) staged in shared; q[64]/o[64] in registers.
// Online softmax with lazy rescale: o/l are rescaled only when the running
// max changes (expected ~ln(S) times per row).
// Causality handled exactly by per-thread kmax (no masked work executed).
// ============================================================================
__global__ __launch_bounds__(128)
void flash_attn_kernel()
{
    __shared__ float Ks[64][64];
    __shared__ float Vs[64][64];

    const int tid = threadIdx.x;
    const int r   = blockIdx.x * 128 + tid;   // global query row in sequence
    const int h   = blockIdx.y;
    const int b   = blockIdx.z;

    const float* Qp = g_q + ((size_t)(b * Sn + r)) * Dn + h * HDn;

    float q[64];
#pragma unroll
    for (int d = 0; d < 64; d += 4) {
        float4 t = *(const float4*)(Qp + d);
        q[d] = t.x; q[d + 1] = t.y; q[d + 2] = t.z; q[d + 3] = t.w;
    }

    float o[64];
#pragma unroll
    for (int d = 0; d < 64; d++) o[d] = 0.f;
    float m = -1e30f;
    float l = 0.f;

    const int nkt = (blockIdx.x + 1) * 2;  // 64-wide k tiles covering causal span

    for (int kt = 0; kt < nkt; kt++) {
        // cooperative load of K and V tiles (coalesced, float4)
        const float* Kp = g_k + ((size_t)(b * Sn + kt * 64)) * Dn + h * HDn;
        const float* Vp = g_v + ((size_t)(b * Sn + kt * 64)) * Dn + h * HDn;
#pragma unroll
        for (int idx = tid; idx < 64 * 16; idx += 128) {
            const int row = idx >> 4;
            const int c4  = (idx & 15) * 4;
            *(float4*)&Ks[row][c4] = *(const float4*)(Kp + (size_t)row * Dn + c4);
            *(float4*)&Vs[row][c4] = *(const float4*)(Vp + (size_t)row * Dn + c4);
        }
        __syncthreads();

        if (kt * 64 <= r) {
            const int kmax = min(64, r - kt * 64 + 1);
            for (int k = 0; k < kmax; k++) {
                // dot(q, K[k]) with 4 independent FFMA chains
                float s0 = 0.f, s1 = 0.f, s2 = 0.f, s3 = 0.f;
#pragma unroll
                for (int d = 0; d < 64; d += 4) {
                    s0 += q[d + 0] * Ks[k][d + 0];
                    s1 += q[d + 1] * Ks[k][d + 1];
                    s2 += q[d + 2] * Ks[k][d + 2];
                    s3 += q[d + 3] * Ks[k][d + 3];
                }
                float s = ((s0 + s1) + (s2 + s3)) * 0.125f;  // 1/sqrt(64)

                if (s > m) {  // rare: new running max -> rescale o, l
                    const float corr = __expf(m - s);
                    l *= corr;
#pragma unroll
                    for (int d = 0; d < 64; d++) o[d] *= corr;
                    m = s;
                }
                const float p = __expf(s - m);
                l += p;
                // accumulate in 4 independent chains (o[d] regs are distinct,
                // but grouping helps the scheduler interleave LDS/FFMA)
#pragma unroll
                for (int d = 0; d < 64; d += 4) {
                    o[d + 0] += p * Vs[k][d + 0];
                    o[d + 1] += p * Vs[k][d + 1];
                    o[d + 2] += p * Vs[k][d + 2];
                    o[d + 3] += p * Vs[k][d + 3];
                }
            }
        }
        __syncthreads();
    }

    const float inv = 1.f / l;
    float* Op = g_o + ((size_t)(b * Sn + r)) * Dn + h * HDn;
#pragma unroll
    for (int d = 0; d < 64; d += 4) {
        float4 t;
        t.x = o[d + 0] * inv;
        t.y = o[d + 1] * inv;
        t.z = o[d + 2] * inv;
        t.w = o[d + 3] * inv;
        *(float4*)(Op + d) = t;
    }
}

// ============================================================================
// launch
// ============================================================================
extern "C" void kernel_launch(void* const* d_in, const int* in_sizes, int n_in,
                              void* d_out, int out_size)
{
    const float* x    = (const float*)d_in[0];
    const float* w_q  = (const float*)d_in[1];
    const float* b_q  = (const float*)d_in[2];
    const float* w_k  = (const float*)d_in[3];
    const float* b_k  = (const float*)d_in[4];
    const float* w_v  = (const float*)d_in[5];
    const float* b_v  = (const float*)d_in[6];
    const float* w_o  = (const float*)d_in[7];
    const float* b_o  = (const float*)d_in[8];
    float* out = (float*)d_out;

    // Q, K, V projections (fused into one launch via gridDim.z)
    {
        dim3 grid(Dn / 128, Mn / 128, 3);   // (8, 32, 3)
        sgemm_qkv_kernel<<<grid, 256>>>(x, w_q, b_q, w_k, b_k, w_v, b_v);
    }

    // causal flash attention
    {
        dim3 grid(Sn / 128, Hn, Bn);        // (16, 16, 2)
        flash_attn_kernel<<<grid, 128>>>();
    }

    // output projection
    {
        dim3 grid(Dn / 128, Mn / 128, 1);   // (8, 32)
        sgemm_out_kernel<<<grid, 256>>>(w_o, b_o, out);
    }
}

// round 9
// speedup vs baseline: 1.4355x; 1.4355x over previous
#include <cuda_runtime.h>
#include <cuda_bf16.h>
#include <cstdint>

// Problem constants
#define Bn 2
#define Sn 2048
#define Dn 1024
#define Hn 16
#define HDn 64
#define Mn (Bn * Sn)          // 4096 rows for the projection GEMMs

// -------- scratch (no allocations allowed; device globals) --------
__device__ float g_q[Bn * Sn * Dn];   // 16 MiB
__device__ float g_k[Bn * Sn * Dn];   // 16 MiB
__device__ float g_v[Bn * Sn * Dn];   // 16 MiB
__device__ float g_o[Bn * Sn * Dn];   // 16 MiB (attention output, pre out-proj)

// ============================================================================
// PTX helpers — ONLY arch-portable instructions (ldmatrix sm_75+,
// mma.sync bf16 sm_80+). NO tcgen05: harness ptxas targets base sm_103.
// ============================================================================
__device__ __forceinline__ uint32_t smem_to_u32(const void* p) {
    uint32_t a;
    asm("{ .reg .u64 t; cvta.to.shared.u64 t, %1; cvt.u32.u64 %0, t; }"
        : "=r"(a) : "l"(p));
    return a;
}

__device__ __forceinline__ void ldsm_x4(uint32_t r[4], uint32_t addr) {
    asm volatile("ldmatrix.sync.aligned.m8n8.x4.shared.b16 {%0,%1,%2,%3}, [%4];"
        : "=r"(r[0]), "=r"(r[1]), "=r"(r[2]), "=r"(r[3]) : "r"(addr));
}

__device__ __forceinline__ void mma16816(float c[4], const uint32_t a[4],
                                         uint32_t b0, uint32_t b1) {
    asm volatile(
        "mma.sync.aligned.m16n8k16.row.col.f32.bf16.bf16.f32 "
        "{%0,%1,%2,%3}, {%4,%5,%6,%7}, {%8,%9}, {%0,%1,%2,%3};"
        : "+f"(c[0]), "+f"(c[1]), "+f"(c[2]), "+f"(c[3])
        : "r"(a[0]), "r"(a[1]), "r"(a[2]), "r"(a[3]), "r"(b0), "r"(b1));
}

// pack hi-16-bits of two fp32 into one reg: {lo16=hi(f0), hi16=hi(f1)}
__device__ __forceinline__ uint32_t prmt_hi(uint32_t a, uint32_t b) {
    uint32_t r;
    asm("prmt.b32 %0, %1, %2, 0x7632;" : "=r"(r) : "r"(a), "r"(b));
    return r;
}

__device__ __forceinline__ uint32_t cvt_bf16x2(float hi_f, float lo_f) {
    uint32_t r;  // r[15:0] = bf16(lo_f), r[31:16] = bf16(hi_f)
    asm("cvt.rn.bf16x2.f32 %0, %1, %2;" : "=r"(r) : "f"(hi_f), "f"(lo_f));
    return r;
}

// ============================================================================
// mma.sync split-bf16 GEMM (NT): C[m,n] = sum_k A[m,k]*W[n,k] + bias[n]
// A [M,K] fp32 row-major, W [N,K] fp32 row-major. K = N = 1024.
// CTA tile 128x128, 8 warps of 64x32, K-chunk 32 fp32, double-buffered smem.
// Split: Ah = trunc16(A) (exact), Al = bf16(A - Ah); 3 products per tile:
// D += Ah*Bh + Ah*Bl + Al*Bh (drop Al*Bl ~ 2^-14), fp32 accumulators.
// smem per matrix: 128 rows x 80B (32 bf16 + 8 pad) -> conflict-free ldmatrix.
// ============================================================================
#define KC 32                 // fp32 k per chunk
#define NCH (Dn / KC)         // 32 chunks
#define RSTRIDE 80            // smem row stride bytes
#define MATB (128 * RSTRIDE)  // 10240 per matrix
#define OFF_AH 0
#define OFF_AL (MATB)
#define OFF_BH (2 * MATB)
#define OFF_BL (3 * MATB)
#define STAGE (4 * MATB)      // 40960
#define GEMM_SMEM (2 * STAGE) // 81920

__device__ __forceinline__ void split_store(char* hi_mat, char* lo_mat,
                                            int row, int c4, float4 f)
{
    uint32_t u0 = __float_as_uint(f.x), u1 = __float_as_uint(f.y);
    uint32_t u2 = __float_as_uint(f.z), u3 = __float_as_uint(f.w);
    uint32_t h01 = prmt_hi(u0, u1);
    uint32_t h23 = prmt_hi(u2, u3);
    float t0 = __uint_as_float(u0 & 0xFFFF0000u);
    float t1 = __uint_as_float(u1 & 0xFFFF0000u);
    float t2 = __uint_as_float(u2 & 0xFFFF0000u);
    float t3 = __uint_as_float(u3 & 0xFFFF0000u);
    uint32_t l01 = cvt_bf16x2(f.y - t1, f.x - t0);
    uint32_t l23 = cvt_bf16x2(f.w - t3, f.z - t2);
    const int off = row * RSTRIDE + c4 * 2;
    *(uint2*)(hi_mat + off) = make_uint2(h01, h23);
    *(uint2*)(lo_mat + off) = make_uint2(l01, l23);
}

__device__ __forceinline__ void gemm_mma_body(const float* __restrict__ A,
                                              const float* __restrict__ W,
                                              const float* __restrict__ bias,
                                              float* __restrict__ C)
{
    extern __shared__ char smem[];
    const uint32_t smem_u = smem_to_u32(smem);
    const int tid  = threadIdx.x;
    const int wid  = tid >> 5;
    const int lane = tid & 31;
    const int cCol = blockIdx.x;     // N tile
    const int cRow = blockIdx.y;     // M tile
    const int wr = wid >> 2;         // warp m offset: wr*64
    const int wc = wid & 3;          // warp n offset: wc*32

    float acc[16][4];
#pragma unroll
    for (int t = 0; t < 16; t++)
#pragma unroll
        for (int j = 0; j < 4; j++) acc[t][j] = 0.f;

    const float* GA = A + (size_t)(cRow * 128) * Dn;
    const float* GB = W + (size_t)(cCol * 128) * Dn;

    // loader mapping: 1024 float4 per matrix per chunk; 4 per thread
    int lrow[4], lc4[4];
#pragma unroll
    for (int p = 0; p < 4; p++) {
        const int idx = p * 256 + tid;
        lrow[p] = idx >> 3;          // 0..127
        lc4[p]  = (idx & 7) * 4;     // 0..28
    }

    // prologue: chunk 0 -> buffer 0
#pragma unroll
    for (int p = 0; p < 4; p++) {
        float4 fa = *(const float4*)(GA + (size_t)lrow[p] * Dn + lc4[p]);
        float4 fb = *(const float4*)(GB + (size_t)lrow[p] * Dn + lc4[p]);
        split_store(smem + OFF_AH, smem + OFF_AL, lrow[p], lc4[p], fa);
        split_store(smem + OFF_BH, smem + OFF_BL, lrow[p], lc4[p], fb);
    }
    __syncthreads();

    // ldmatrix per-lane addressing: row-in-16 = lane&15, col16 = (lane&16)?16:0
    const int lr16 = lane & 15;
    const int lc16 = (lane & 16) ? 16 : 0;

    for (int i = 0; i < NCH; i++) {
        const int b = i & 1;

        // prefetch next chunk into registers
        float4 pa[4], pb[4];
        if (i + 1 < NCH) {
            const int k0 = (i + 1) * KC;
#pragma unroll
            for (int p = 0; p < 4; p++) {
                pa[p] = *(const float4*)(GA + (size_t)lrow[p] * Dn + k0 + lc4[p]);
                pb[p] = *(const float4*)(GB + (size_t)lrow[p] * Dn + k0 + lc4[p]);
            }
        }

        // compute on buffer b (2 k-steps of 16)
        const uint32_t base = smem_u + b * STAGE;
#pragma unroll
        for (int ks = 0; ks < 2; ks++) {
            const int cb = ks * 32 + lc16;
            uint32_t ah[4][4], al[4][4], bh[2][4], bl[2][4];
#pragma unroll
            for (int mt = 0; mt < 4; mt++) {
                const uint32_t ad = base + OFF_AH +
                    (uint32_t)((wr * 64 + mt * 16 + lr16) * RSTRIDE + cb);
                ldsm_x4(ah[mt], ad);
                ldsm_x4(al[mt], ad + MATB);
            }
#pragma unroll
            for (int np = 0; np < 2; np++) {
                const uint32_t bd = base + OFF_BH +
                    (uint32_t)((wc * 32 + np * 16 + lr16) * RSTRIDE + cb);
                ldsm_x4(bh[np], bd);
                ldsm_x4(bl[np], bd + MATB);
            }
#pragma unroll
            for (int mt = 0; mt < 4; mt++) {
#pragma unroll
                for (int nt = 0; nt < 4; nt++) {
                    const int np = nt >> 1, hf = nt & 1;
                    float* c = acc[mt * 4 + nt];
                    mma16816(c, ah[mt], bh[np][hf], bh[np][hf + 2]);
                    mma16816(c, ah[mt], bl[np][hf], bl[np][hf + 2]);
                    mma16816(c, al[mt], bh[np][hf], bh[np][hf + 2]);
                }
            }
        }

        // stage prefetched chunk into other buffer, single barrier
        if (i + 1 < NCH) {
            char* obuf = smem + (b ^ 1) * STAGE;
#pragma unroll
            for (int p = 0; p < 4; p++) {
                split_store(obuf + OFF_AH, obuf + OFF_AL, lrow[p], lc4[p], pa[p]);
                split_store(obuf + OFF_BH, obuf + OFF_BL, lrow[p], lc4[p], pb[p]);
            }
            __syncthreads();
        }
    }

    // epilogue: D fragment: c0,c1 at (row=lane>>2, col=2*(lane&3)); c2,c3 at row+8
    const int r0 = lane >> 2;
    const int c0 = (lane & 3) * 2;
#pragma unroll
    for (int mt = 0; mt < 4; mt++) {
#pragma unroll
        for (int nt = 0; nt < 4; nt++) {
            const float* c = acc[mt * 4 + nt];
            const int grow = cRow * 128 + wr * 64 + mt * 16 + r0;
            const int gcol = cCol * 128 + wc * 32 + nt * 8 + c0;
            const float b0 = bias[gcol], b1 = bias[gcol + 1];
            float2 v0 = make_float2(c[0] + b0, c[1] + b1);
            float2 v1 = make_float2(c[2] + b0, c[3] + b1);
            *(float2*)(C + (size_t)grow * Dn + gcol) = v0;
            *(float2*)(C + (size_t)(grow + 8) * Dn + gcol) = v1;
        }
    }
}

// Fused Q/K/V projection (gridDim.z selects target)
__global__ __launch_bounds__(256, 1)
void gemm_qkv_mma_kernel(const float* __restrict__ x,
                         const float* __restrict__ wq, const float* __restrict__ bq,
                         const float* __restrict__ wk, const float* __restrict__ bk,
                         const float* __restrict__ wv, const float* __restrict__ bv)
{
    const float* W;
    const float* bias;
    float* out;
    if (blockIdx.z == 0)      { W = wq; bias = bq; out = g_q; }
    else if (blockIdx.z == 1) { W = wk; bias = bk; out = g_k; }
    else                      { W = wv; bias = bv; out = g_v; }
    gemm_mma_body(x, W, bias, out);
}

__global__ __launch_bounds__(256, 1)
void gemm_out_mma_kernel(const float* __restrict__ wout,
                         const float* __restrict__ bout,
                         float* __restrict__ out)
{
    gemm_mma_body(g_o, wout, bout, out);
}

// ============================================================================
// Causal flash attention (fp32). Heavy q-tiles scheduled FIRST (qt remap)
// so the 16x causal work spread doesn't land the longest blocks in the tail
// wave. Core loop identical to the R3 kernel that passed (rel_err 1.2e-6).
// ============================================================================
__global__ __launch_bounds__(128)
void flash_attn_kernel()
{
    __shared__ float Ks[64][64];
    __shared__ float Vs[64][64];

    const int tid = threadIdx.x;
    const int qt  = gridDim.x - 1 - blockIdx.x;   // heavy tiles first
    const int r   = qt * 128 + tid;               // global query row
    const int h   = blockIdx.y;
    const int b   = blockIdx.z;

    const float* Qp = g_q + ((size_t)(b * Sn + r)) * Dn + h * HDn;

    float q[64];
#pragma unroll
    for (int d = 0; d < 64; d += 4) {
        float4 t = *(const float4*)(Qp + d);
        q[d] = t.x; q[d + 1] = t.y; q[d + 2] = t.z; q[d + 3] = t.w;
    }

    float o[64];
#pragma unroll
    for (int d = 0; d < 64; d++) o[d] = 0.f;
    float m = -1e30f;
    float l = 0.f;

    const int nkt = (qt + 1) * 2;  // 64-wide k tiles covering causal span

    for (int kt = 0; kt < nkt; kt++) {
        const float* Kp = g_k + ((size_t)(b * Sn + kt * 64)) * Dn + h * HDn;
        const float* Vp = g_v + ((size_t)(b * Sn + kt * 64)) * Dn + h * HDn;
#pragma unroll
        for (int idx = tid; idx < 64 * 16; idx += 128) {
            const int row = idx >> 4;
            const int c4  = (idx & 15) * 4;
            *(float4*)&Ks[row][c4] = *(const float4*)(Kp + (size_t)row * Dn + c4);
            *(float4*)&Vs[row][c4] = *(const float4*)(Vp + (size_t)row * Dn + c4);
        }
        __syncthreads();

        if (kt * 64 <= r) {
            const int kmax = min(64, r - kt * 64 + 1);
            for (int k = 0; k < kmax; k++) {
                float s0 = 0.f, s1 = 0.f, s2 = 0.f, s3 = 0.f;
#pragma unroll
                for (int d = 0; d < 64; d += 4) {
                    s0 += q[d + 0] * Ks[k][d + 0];
                    s1 += q[d + 1] * Ks[k][d + 1];
                    s2 += q[d + 2] * Ks[k][d + 2];
                    s3 += q[d + 3] * Ks[k][d + 3];
                }
                float s = ((s0 + s1) + (s2 + s3)) * 0.125f;

                if (s > m) {
                    const float corr = __expf(m - s);
                    l *= corr;
#pragma unroll
                    for (int d = 0; d < 64; d++) o[d] *= corr;
                    m = s;
                }
                const float p = __expf(s - m);
                l += p;
#pragma unroll
                for (int d = 0; d < 64; d += 4) {
                    o[d + 0] += p * Vs[k][d + 0];
                    o[d + 1] += p * Vs[k][d + 1];
                    o[d + 2] += p * Vs[k][d + 2];
                    o[d + 3] += p * Vs[k][d + 3];
                }
            }
        }
        __syncthreads();
    }

    const float inv = 1.f / l;
    float* Op = g_o + ((size_t)(b * Sn + r)) * Dn + h * HDn;
#pragma unroll
    for (int d = 0; d < 64; d += 4) {
        float4 t;
        t.x = o[d + 0] * inv;
        t.y = o[d + 1] * inv;
        t.z = o[d + 2] * inv;
        t.w = o[d + 3] * inv;
        *(float4*)(Op + d) = t;
    }
}

// ============================================================================
// launch
// ============================================================================
extern "C" void kernel_launch(void* const* d_in, const int* in_sizes, int n_in,
                              void* d_out, int out_size)
{
    const float* x    = (const float*)d_in[0];
    const float* w_q  = (const float*)d_in[1];
    const float* b_q  = (const float*)d_in[2];
    const float* w_k  = (const float*)d_in[3];
    const float* b_k  = (const float*)d_in[4];
    const float* w_v  = (const float*)d_in[5];
    const float* b_v  = (const float*)d_in[6];
    const float* w_o  = (const float*)d_in[7];
    const float* b_o  = (const float*)d_in[8];
    float* out = (float*)d_out;

    // allow >48KB dynamic smem (idempotent; capture-safe)
    cudaFuncSetAttribute(gemm_qkv_mma_kernel,
                         cudaFuncAttributeMaxDynamicSharedMemorySize, GEMM_SMEM);
    cudaFuncSetAttribute(gemm_out_mma_kernel,
                         cudaFuncAttributeMaxDynamicSharedMemorySize, GEMM_SMEM);

    // Q, K, V projections (mma.sync split-bf16)
    {
        dim3 grid(Dn / 128, Mn / 128, 3);   // (8, 32, 3)
        gemm_qkv_mma_kernel<<<grid, 256, GEMM_SMEM>>>(x, w_q, b_q, w_k, b_k, w_v, b_v);
    }

    // causal flash attention
    {
        dim3 grid(Sn / 128, Hn, Bn);        // (16, 16, 2)
        flash_attn_kernel<<<grid, 128>>>();
    }

    // output projection (mma.sync split-bf16)
    {
        dim3 grid(Dn / 128, Mn / 128, 1);   // (8, 32)
        gemm_out_mma_kernel<<<grid, 256, GEMM_SMEM>>>(w_o, b_o, out);
    }
}

// round 10
// speedup vs baseline: 2.7425x; 1.9105x over previous
#include <cuda_runtime.h>
#include <cuda_bf16.h>
#include <cstdint>

// Problem constants
#define Bn 2
#define Sn 2048
#define Dn 1024
#define Hn 16
#define HDn 64
#define Mn (Bn * Sn)          // 4096 rows for the projection GEMMs

// -------- scratch (no allocations allowed; device globals) --------
__device__ float g_q[Bn * Sn * Dn];   // 16 MiB
__device__ float g_k[Bn * Sn * Dn];   // 16 MiB
__device__ float g_v[Bn * Sn * Dn];   // 16 MiB
__device__ float g_o[Bn * Sn * Dn];   // 16 MiB (attention output, pre out-proj)

// ============================================================================
// PTX helpers — ONLY arch-portable instructions (ldmatrix sm_75+,
// mma.sync bf16 sm_80+). NO tcgen05: harness ptxas targets base sm_103.
// ============================================================================
__device__ __forceinline__ uint32_t smem_to_u32(const void* p) {
    uint32_t a;
    asm("{ .reg .u64 t; cvta.to.shared.u64 t, %1; cvt.u32.u64 %0, t; }"
        : "=r"(a) : "l"(p));
    return a;
}

__device__ __forceinline__ void ldsm_x4(uint32_t r[4], uint32_t addr) {
    asm volatile("ldmatrix.sync.aligned.m8n8.x4.shared.b16 {%0,%1,%2,%3}, [%4];"
        : "=r"(r[0]), "=r"(r[1]), "=r"(r[2]), "=r"(r[3]) : "r"(addr));
}

__device__ __forceinline__ void ldsm_x4_t(uint32_t r[4], uint32_t addr) {
    asm volatile("ldmatrix.sync.aligned.m8n8.x4.trans.shared.b16 {%0,%1,%2,%3}, [%4];"
        : "=r"(r[0]), "=r"(r[1]), "=r"(r[2]), "=r"(r[3]) : "r"(addr));
}

__device__ __forceinline__ void mma16816(float c[4], const uint32_t a[4],
                                         uint32_t b0, uint32_t b1) {
    asm volatile(
        "mma.sync.aligned.m16n8k16.row.col.f32.bf16.bf16.f32 "
        "{%0,%1,%2,%3}, {%4,%5,%6,%7}, {%8,%9}, {%0,%1,%2,%3};"
        : "+f"(c[0]), "+f"(c[1]), "+f"(c[2]), "+f"(c[3])
        : "r"(a[0]), "r"(a[1]), "r"(a[2]), "r"(a[3]), "r"(b0), "r"(b1));
}

// pack hi-16-bits of two fp32 into one reg: {lo16=hi(f0), hi16=hi(f1)}
__device__ __forceinline__ uint32_t prmt_hi(uint32_t a, uint32_t b) {
    uint32_t r;
    asm("prmt.b32 %0, %1, %2, 0x7632;" : "=r"(r) : "r"(a), "r"(b));
    return r;
}

__device__ __forceinline__ uint32_t cvt_bf16x2(float hi_f, float lo_f) {
    uint32_t r;  // r[15:0] = bf16(lo_f), r[31:16] = bf16(hi_f)
    asm("cvt.rn.bf16x2.f32 %0, %1, %2;" : "=r"(r) : "f"(hi_f), "f"(lo_f));
    return r;
}

// truncation split of two fp32 into packed bf16x2 hi (exact) + lo (residual)
__device__ __forceinline__ void split_pack(float v0, float v1,
                                           uint32_t& hi, uint32_t& lo) {
    uint32_t u0 = __float_as_uint(v0), u1 = __float_as_uint(v1);
    hi = prmt_hi(u0, u1);
    float t0 = __uint_as_float(u0 & 0xFFFF0000u);
    float t1 = __uint_as_float(u1 & 0xFFFF0000u);
    lo = cvt_bf16x2(v1 - t1, v0 - t0);
}

// ============================================================================
// mma.sync split-bf16 GEMM (NT) — UNCHANGED from R9 (passed, rel 4.7e-5).
// ============================================================================
#define KC 32
#define NCH (Dn / KC)
#define RSTRIDE 80
#define MATB (128 * RSTRIDE)
#define OFF_AH 0
#define OFF_AL (MATB)
#define OFF_BH (2 * MATB)
#define OFF_BL (3 * MATB)
#define STAGE (4 * MATB)
#define GEMM_SMEM (2 * STAGE)

__device__ __forceinline__ void split_store(char* hi_mat, char* lo_mat,
                                            int row, int c4, float4 f)
{
    uint32_t u0 = __float_as_uint(f.x), u1 = __float_as_uint(f.y);
    uint32_t u2 = __float_as_uint(f.z), u3 = __float_as_uint(f.w);
    uint32_t h01 = prmt_hi(u0, u1);
    uint32_t h23 = prmt_hi(u2, u3);
    float t0 = __uint_as_float(u0 & 0xFFFF0000u);
    float t1 = __uint_as_float(u1 & 0xFFFF0000u);
    float t2 = __uint_as_float(u2 & 0xFFFF0000u);
    float t3 = __uint_as_float(u3 & 0xFFFF0000u);
    uint32_t l01 = cvt_bf16x2(f.y - t1, f.x - t0);
    uint32_t l23 = cvt_bf16x2(f.w - t3, f.z - t2);
    const int off = row * RSTRIDE + c4 * 2;
    *(uint2*)(hi_mat + off) = make_uint2(h01, h23);
    *(uint2*)(lo_mat + off) = make_uint2(l01, l23);
}

__device__ __forceinline__ void gemm_mma_body(const float* __restrict__ A,
                                              const float* __restrict__ W,
                                              const float* __restrict__ bias,
                                              float* __restrict__ C)
{
    extern __shared__ char smem[];
    const uint32_t smem_u = smem_to_u32(smem);
    const int tid  = threadIdx.x;
    const int wid  = tid >> 5;
    const int lane = tid & 31;
    const int cCol = blockIdx.x;
    const int cRow = blockIdx.y;
    const int wr = wid >> 2;
    const int wc = wid & 3;

    float acc[16][4];
#pragma unroll
    for (int t = 0; t < 16; t++)
#pragma unroll
        for (int j = 0; j < 4; j++) acc[t][j] = 0.f;

    const float* GA = A + (size_t)(cRow * 128) * Dn;
    const float* GB = W + (size_t)(cCol * 128) * Dn;

    int lrow[4], lc4[4];
#pragma unroll
    for (int p = 0; p < 4; p++) {
        const int idx = p * 256 + tid;
        lrow[p] = idx >> 3;
        lc4[p]  = (idx & 7) * 4;
    }

#pragma unroll
    for (int p = 0; p < 4; p++) {
        float4 fa = *(const float4*)(GA + (size_t)lrow[p] * Dn + lc4[p]);
        float4 fb = *(const float4*)(GB + (size_t)lrow[p] * Dn + lc4[p]);
        split_store(smem + OFF_AH, smem + OFF_AL, lrow[p], lc4[p], fa);
        split_store(smem + OFF_BH, smem + OFF_BL, lrow[p], lc4[p], fb);
    }
    __syncthreads();

    const int lr16 = lane & 15;
    const int lc16 = (lane & 16) ? 16 : 0;

    for (int i = 0; i < NCH; i++) {
        const int b = i & 1;

        float4 pa[4], pb[4];
        if (i + 1 < NCH) {
            const int k0 = (i + 1) * KC;
#pragma unroll
            for (int p = 0; p < 4; p++) {
                pa[p] = *(const float4*)(GA + (size_t)lrow[p] * Dn + k0 + lc4[p]);
                pb[p] = *(const float4*)(GB + (size_t)lrow[p] * Dn + k0 + lc4[p]);
            }
        }

        const uint32_t base = smem_u + b * STAGE;
#pragma unroll
        for (int ks = 0; ks < 2; ks++) {
            const int cb = ks * 32 + lc16;
            uint32_t ah[4][4], al[4][4], bh[2][4], bl[2][4];
#pragma unroll
            for (int mt = 0; mt < 4; mt++) {
                const uint32_t ad = base + OFF_AH +
                    (uint32_t)((wr * 64 + mt * 16 + lr16) * RSTRIDE + cb);
                ldsm_x4(ah[mt], ad);
                ldsm_x4(al[mt], ad + MATB);
            }
#pragma unroll
            for (int np = 0; np < 2; np++) {
                const uint32_t bd = base + OFF_BH +
                    (uint32_t)((wc * 32 + np * 16 + lr16) * RSTRIDE + cb);
                ldsm_x4(bh[np], bd);
                ldsm_x4(bl[np], bd + MATB);
            }
#pragma unroll
            for (int mt = 0; mt < 4; mt++) {
#pragma unroll
                for (int nt = 0; nt < 4; nt++) {
                    const int np = nt >> 1, hf = nt & 1;
                    float* c = acc[mt * 4 + nt];
                    mma16816(c, ah[mt], bh[np][hf], bh[np][hf + 2]);
                    mma16816(c, ah[mt], bl[np][hf], bl[np][hf + 2]);
                    mma16816(c, al[mt], bh[np][hf], bh[np][hf + 2]);
                }
            }
        }

        if (i + 1 < NCH) {
            char* obuf = smem + (b ^ 1) * STAGE;
#pragma unroll
            for (int p = 0; p < 4; p++) {
                split_store(obuf + OFF_AH, obuf + OFF_AL, lrow[p], lc4[p], pa[p]);
                split_store(obuf + OFF_BH, obuf + OFF_BL, lrow[p], lc4[p], pb[p]);
            }
            __syncthreads();
        }
    }

    const int r0 = lane >> 2;
    const int c0 = (lane & 3) * 2;
#pragma unroll
    for (int mt = 0; mt < 4; mt++) {
#pragma unroll
        for (int nt = 0; nt < 4; nt++) {
            const float* c = acc[mt * 4 + nt];
            const int grow = cRow * 128 + wr * 64 + mt * 16 + r0;
            const int gcol = cCol * 128 + wc * 32 + nt * 8 + c0;
            const float b0 = bias[gcol], b1 = bias[gcol + 1];
            float2 v0 = make_float2(c[0] + b0, c[1] + b1);
            float2 v1 = make_float2(c[2] + b0, c[3] + b1);
            *(float2*)(C + (size_t)grow * Dn + gcol) = v0;
            *(float2*)(C + (size_t)(grow + 8) * Dn + gcol) = v1;
        }
    }
}

__global__ __launch_bounds__(256, 1)
void gemm_qkv_mma_kernel(const float* __restrict__ x,
                         const float* __restrict__ wq, const float* __restrict__ bq,
                         const float* __restrict__ wk, const float* __restrict__ bk,
                         const float* __restrict__ wv, const float* __restrict__ bv)
{
    const float* W;
    const float* bias;
    float* out;
    if (blockIdx.z == 0)      { W = wq; bias = bq; out = g_q; }
    else if (blockIdx.z == 1) { W = wk; bias = bk; out = g_k; }
    else                      { W = wv; bias = bv; out = g_v; }
    gemm_mma_body(x, W, bias, out);
}

__global__ __launch_bounds__(256, 1)
void gemm_out_mma_kernel(const float* __restrict__ wout,
                         const float* __restrict__ bout,
                         float* __restrict__ out)
{
    gemm_mma_body(g_o, wout, bout, out);
}

// ============================================================================
// Tensor-core causal flash attention (split-bf16 mma.sync, fp32 softmax).
// Block: 128 threads (4 warps), 64 q-rows x 1 head. Q frags register-resident.
// Per 64-key tile: S = QK^T (3-product split), online softmax in accumulator
// fragments, P re-packed to A-frags in registers, O += P V with ldmatrix.trans
// V fragments (3-product split). Causal: warp-level group bound on diagonal
// tile + element mask. Heavy q-tiles scheduled first.
// ============================================================================
#define ARST 144                         // smem row stride bytes (64 bf16 + pad)
#define AQH 0
#define AQL (64 * ARST)
#define AKH (2 * 64 * ARST)
#define AKL (3 * 64 * ARST)
#define AVH (4 * 64 * ARST)
#define AVL (5 * 64 * ARST)
#define ATT_SMEM (6 * 64 * ARST)         // 55296 bytes

__device__ __forceinline__ void split_store_a(char* hi_mat, char* lo_mat,
                                              int row, int c4, float4 f)
{
    uint32_t u0 = __float_as_uint(f.x), u1 = __float_as_uint(f.y);
    uint32_t u2 = __float_as_uint(f.z), u3 = __float_as_uint(f.w);
    uint32_t h01 = prmt_hi(u0, u1);
    uint32_t h23 = prmt_hi(u2, u3);
    float t0 = __uint_as_float(u0 & 0xFFFF0000u);
    float t1 = __uint_as_float(u1 & 0xFFFF0000u);
    float t2 = __uint_as_float(u2 & 0xFFFF0000u);
    float t3 = __uint_as_float(u3 & 0xFFFF0000u);
    uint32_t l01 = cvt_bf16x2(f.y - t1, f.x - t0);
    uint32_t l23 = cvt_bf16x2(f.w - t3, f.z - t2);
    const int off = row * ARST + c4 * 2;
    *(uint2*)(hi_mat + off) = make_uint2(h01, h23);
    *(uint2*)(lo_mat + off) = make_uint2(l01, l23);
}

__global__ __launch_bounds__(128)
void flash_attn_mma_kernel()
{
    extern __shared__ char smem[];
    const uint32_t smem_u = smem_to_u32(smem);
    const int tid  = threadIdx.x;
    const int wid  = tid >> 5;
    const int lane = tid & 31;
    const int qt = gridDim.x - 1 - blockIdx.x;   // heavy tiles first
    const int h  = blockIdx.y;
    const int b  = blockIdx.z;

    const int lr16 = lane & 15;
    const int lc16 = (lane & 16) ? 16 : 0;
    const int rbase = wid * 16 + (lane >> 2);    // lane's low row within q-tile
    const int cquad = (lane & 3) * 2;

    // ---- stage Q tile (64 x 64 fp32 of this head), split to bf16 hi/lo ----
    {
        const float* GQ = g_q + ((size_t)(b * Sn + qt * 64)) * Dn + h * HDn;
#pragma unroll
        for (int p = 0; p < 8; p++) {
            const int idx = p * 128 + tid;
            const int row = idx >> 4;
            const int c4  = (idx & 15) * 4;
            float4 f = *(const float4*)(GQ + (size_t)row * Dn + c4);
            split_store_a(smem + AQH, smem + AQL, row, c4, f);
        }
    }
    __syncthreads();

    // Q fragments, register-resident for the whole block
    uint32_t qh[4][4], ql[4][4];
#pragma unroll
    for (int kc = 0; kc < 4; kc++) {
        const uint32_t ad = smem_u + AQH +
            (uint32_t)((wid * 16 + lr16) * ARST + kc * 32 + lc16);
        ldsm_x4(qh[kc], ad);
        ldsm_x4(ql[kc], ad + (AQL - AQH));
    }

    float s[8][4];
    float o[8][4];
#pragma unroll
    for (int f = 0; f < 8; f++)
#pragma unroll
        for (int j = 0; j < 4; j++) o[f][j] = 0.f;
    float m0 = -1e30f, m1 = -1e30f, l0 = 0.f, l1 = 0.f;

    for (int kt = 0; kt <= qt; kt++) {
        __syncthreads();   // previous tile's smem reads complete before overwrite

        // ---- stage K, V tiles (64 keys x 64 dims), split hi/lo ----
        const float* GK = g_k + ((size_t)(b * Sn + kt * 64)) * Dn + h * HDn;
        const float* GV = g_v + ((size_t)(b * Sn + kt * 64)) * Dn + h * HDn;
#pragma unroll
        for (int p = 0; p < 8; p++) {
            const int idx = p * 128 + tid;
            const int row = idx >> 4;
            const int c4  = (idx & 15) * 4;
            float4 fk = *(const float4*)(GK + (size_t)row * Dn + c4);
            float4 fv = *(const float4*)(GV + (size_t)row * Dn + c4);
            split_store_a(smem + AKH, smem + AKL, row, c4, fk);
            split_store_a(smem + AVH, smem + AVL, row, c4, fv);
        }
        __syncthreads();

        const bool diag = (kt == qt);
        const int  npb   = diag ? wid : 3;     // key-16-group bound for this warp
        const int  nfrag = (npb + 1) * 2;

        // ---- S = Q K^T (scaled later), fp32 accum ----
#pragma unroll
        for (int nt = 0; nt < 8; nt++) {
            if (nt >= nfrag) continue;
#pragma unroll
            for (int j = 0; j < 4; j++) s[nt][j] = 0.f;
        }
        for (int np = 0; np <= npb; np++) {
            uint32_t kbh[4][4], kbl[4][4];
#pragma unroll
            for (int kc = 0; kc < 4; kc++) {
                const uint32_t ad = smem_u + AKH +
                    (uint32_t)((np * 16 + lr16) * ARST + kc * 32 + lc16);
                ldsm_x4(kbh[kc], ad);
                ldsm_x4(kbl[kc], ad + (AKL - AKH));
            }
#pragma unroll
            for (int kc = 0; kc < 4; kc++) {
#pragma unroll
                for (int hf = 0; hf < 2; hf++) {
                    float* c = s[np * 2 + hf];
                    mma16816(c, qh[kc], kbh[kc][hf], kbh[kc][hf + 2]);
                    mma16816(c, qh[kc], kbl[kc][hf], kbl[kc][hf + 2]);
                    mma16816(c, ql[kc], kbh[kc][hf], kbh[kc][hf + 2]);
                }
            }
        }

        // ---- online softmax on fragments (rows r0 = rbase, r1 = rbase+8) ----
        float mt0 = -1e30f, mt1 = -1e30f;
#pragma unroll
        for (int nt = 0; nt < 8; nt++) {
            if (nt >= nfrag) continue;
#pragma unroll
            for (int j = 0; j < 4; j++) {
                float v = s[nt][j] * 0.125f;     // 1/sqrt(64)
                if (diag) {
                    const int col = nt * 8 + cquad + (j & 1);
                    const int r   = rbase + ((j >> 1) << 3);
                    if (col > r) v = -1e30f;
                }
                s[nt][j] = v;
            }
            mt0 = fmaxf(mt0, fmaxf(s[nt][0], s[nt][1]));
            mt1 = fmaxf(mt1, fmaxf(s[nt][2], s[nt][3]));
        }
        mt0 = fmaxf(mt0, __shfl_xor_sync(0xffffffffu, mt0, 1));
        mt0 = fmaxf(mt0, __shfl_xor_sync(0xffffffffu, mt0, 2));
        mt1 = fmaxf(mt1, __shfl_xor_sync(0xffffffffu, mt1, 1));
        mt1 = fmaxf(mt1, __shfl_xor_sync(0xffffffffu, mt1, 2));

        const float mn0 = fmaxf(m0, mt0), mn1 = fmaxf(m1, mt1);
        const float corr0 = __expf(m0 - mn0), corr1 = __expf(m1 - mn1);
        m0 = mn0; m1 = mn1;

        float ls0 = 0.f, ls1 = 0.f;
#pragma unroll
        for (int nt = 0; nt < 8; nt++) {
            if (nt >= nfrag) continue;
            const float p0 = __expf(s[nt][0] - m0);
            const float p1 = __expf(s[nt][1] - m0);
            const float p2 = __expf(s[nt][2] - m1);
            const float p3 = __expf(s[nt][3] - m1);
            ls0 += p0 + p1; ls1 += p2 + p3;
            s[nt][0] = p0; s[nt][1] = p1; s[nt][2] = p2; s[nt][3] = p3;
        }
        ls0 += __shfl_xor_sync(0xffffffffu, ls0, 1);
        ls0 += __shfl_xor_sync(0xffffffffu, ls0, 2);
        ls1 += __shfl_xor_sync(0xffffffffu, ls1, 1);
        ls1 += __shfl_xor_sync(0xffffffffu, ls1, 2);
        l0 = l0 * corr0 + ls0;
        l1 = l1 * corr1 + ls1;

#pragma unroll
        for (int f = 0; f < 8; f++) {
            o[f][0] *= corr0; o[f][1] *= corr0;
            o[f][2] *= corr1; o[f][3] *= corr1;
        }

        // ---- pack P into A-fragments (hi exact-trunc, lo residual) ----
        uint32_t pfh[4][4], pfl[4][4];
#pragma unroll
        for (int g = 0; g < 4; g++) {
            if (g > npb) continue;
            split_pack(s[2 * g][0],     s[2 * g][1],     pfh[g][0], pfl[g][0]);
            split_pack(s[2 * g][2],     s[2 * g][3],     pfh[g][1], pfl[g][1]);
            split_pack(s[2 * g + 1][0], s[2 * g + 1][1], pfh[g][2], pfl[g][2]);
            split_pack(s[2 * g + 1][2], s[2 * g + 1][3], pfh[g][3], pfl[g][3]);
        }

        // ---- O += P V  (V via ldmatrix.trans, split hi/lo) ----
        const int vrow_off = ((lane >> 4) << 3) + (lane & 7);
        const int vcol_off = ((lane >> 3) & 1) * 16;
#pragma unroll
        for (int kc = 0; kc < 4; kc++) {
            if (kc > npb) continue;
            uint32_t vbh[4][4], vbl[4][4];
#pragma unroll
            for (int dg = 0; dg < 4; dg++) {
                const uint32_t ad = smem_u + AVH +
                    (uint32_t)((kc * 16 + vrow_off) * ARST + dg * 32 + vcol_off);
                ldsm_x4_t(vbh[dg], ad);
                ldsm_x4_t(vbl[dg], ad + (AVL - AVH));
            }
#pragma unroll
            for (int dg = 0; dg < 4; dg++) {
#pragma unroll
                for (int hf = 0; hf < 2; hf++) {
                    float* c = o[dg * 2 + hf];
                    mma16816(c, pfh[kc], vbh[dg][hf], vbh[dg][hf + 2]);
                    mma16816(c, pfh[kc], vbl[dg][hf], vbl[dg][hf + 2]);
                    mma16816(c, pfl[kc], vbh[dg][hf], vbh[dg][hf + 2]);
                }
            }
        }
    }

    // ---- epilogue: normalize and store ----
    const float inv0 = 1.f / l0, inv1 = 1.f / l1;
    float* GO = g_o + ((size_t)(b * Sn + qt * 64)) * Dn + h * HDn;
#pragma unroll
    for (int f = 0; f < 8; f++) {
        const int col = f * 8 + cquad;
        const int rlo = wid * 16 + (lane >> 2);
        *(float2*)(GO + (size_t)rlo * Dn + col) =
            make_float2(o[f][0] * inv0, o[f][1] * inv0);
        *(float2*)(GO + (size_t)(rlo + 8) * Dn + col) =
            make_float2(o[f][2] * inv1, o[f][3] * inv1);
    }
}

// ============================================================================
// launch
// ============================================================================
extern "C" void kernel_launch(void* const* d_in, const int* in_sizes, int n_in,
                              void* d_out, int out_size)
{
    const float* x    = (const float*)d_in[0];
    const float* w_q  = (const float*)d_in[1];
    const float* b_q  = (const float*)d_in[2];
    const float* w_k  = (const float*)d_in[3];
    const float* b_k  = (const float*)d_in[4];
    const float* w_v  = (const float*)d_in[5];
    const float* b_v  = (const float*)d_in[6];
    const float* w_o  = (const float*)d_in[7];
    const float* b_o  = (const float*)d_in[8];
    float* out = (float*)d_out;

    // allow >48KB dynamic smem (idempotent; capture-safe)
    cudaFuncSetAttribute(gemm_qkv_mma_kernel,
                         cudaFuncAttributeMaxDynamicSharedMemorySize, GEMM_SMEM);
    cudaFuncSetAttribute(gemm_out_mma_kernel,
                         cudaFuncAttributeMaxDynamicSharedMemorySize, GEMM_SMEM);
    cudaFuncSetAttribute(flash_attn_mma_kernel,
                         cudaFuncAttributeMaxDynamicSharedMemorySize, ATT_SMEM);

    // Q, K, V projections (mma.sync split-bf16)
    {
        dim3 grid(Dn / 128, Mn / 128, 3);   // (8, 32, 3)
        gemm_qkv_mma_kernel<<<grid, 256, GEMM_SMEM>>>(x, w_q, b_q, w_k, b_k, w_v, b_v);
    }

    // causal flash attention (tensor cores)
    {
        dim3 grid(Sn / 64, Hn, Bn);         // (32, 16, 2)
        flash_attn_mma_kernel<<<grid, 128, ATT_SMEM>>>();
    }

    // output projection (mma.sync split-bf16)
    {
        dim3 grid(Dn / 128, Mn / 128, 1);   // (8, 32)
        gemm_out_mma_kernel<<<grid, 256, GEMM_SMEM>>>(w_o, b_o, out);
    }
}

// round 12
// speedup vs baseline: 2.7591x; 1.0060x over previous
#include <cuda_runtime.h>
#include <cuda_bf16.h>
#include <cstdint>

// Problem constants
#define Bn 2
#define Sn 2048
#define Dn 1024
#define Hn 16
#define HDn 64
#define Mn (Bn * Sn)

// -------- pre-split bf16 scratch (no allocations; device globals) --------
__device__ __nv_bfloat16 g_xh[Mn * Dn], g_xl[Mn * Dn];        // x split
__device__ __nv_bfloat16 g_wh[4 * Dn * Dn], g_wl[4 * Dn * Dn];// wq,wk,wv,wo split
__device__ __nv_bfloat16 g_qh[Mn * Dn], g_ql[Mn * Dn];
__device__ __nv_bfloat16 g_kh[Mn * Dn], g_kl[Mn * Dn];
__device__ __nv_bfloat16 g_vh[Mn * Dn], g_vl[Mn * Dn];
__device__ __nv_bfloat16 g_oh[Mn * Dn], g_ol[Mn * Dn];

// ============================================================================
// PTX helpers — arch-portable only (ldmatrix, mma.sync bf16, cp.async).
// ============================================================================
__device__ __forceinline__ uint32_t smem_to_u32(const void* p) {
    uint32_t a;
    asm("{ .reg .u64 t; cvta.to.shared.u64 t, %1; cvt.u32.u64 %0, t; }"
        : "=r"(a) : "l"(p));
    return a;
}

__device__ __forceinline__ void ldsm_x4(uint32_t r[4], uint32_t addr) {
    asm volatile("ldmatrix.sync.aligned.m8n8.x4.shared.b16 {%0,%1,%2,%3}, [%4];"
        : "=r"(r[0]), "=r"(r[1]), "=r"(r[2]), "=r"(r[3]) : "r"(addr));
}

__device__ __forceinline__ void ldsm_x4_t(uint32_t r[4], uint32_t addr) {
    asm volatile("ldmatrix.sync.aligned.m8n8.x4.trans.shared.b16 {%0,%1,%2,%3}, [%4];"
        : "=r"(r[0]), "=r"(r[1]), "=r"(r[2]), "=r"(r[3]) : "r"(addr));
}

__device__ __forceinline__ void mma16816(float c[4], const uint32_t a[4],
                                         uint32_t b0, uint32_t b1) {
    asm volatile(
        "mma.sync.aligned.m16n8k16.row.col.f32.bf16.bf16.f32 "
        "{%0,%1,%2,%3}, {%4,%5,%6,%7}, {%8,%9}, {%0,%1,%2,%3};"
        : "+f"(c[0]), "+f"(c[1]), "+f"(c[2]), "+f"(c[3])
        : "r"(a[0]), "r"(a[1]), "r"(a[2]), "r"(a[3]), "r"(b0), "r"(b1));
}

__device__ __forceinline__ uint32_t prmt_hi(uint32_t a, uint32_t b) {
    uint32_t r;
    asm("prmt.b32 %0, %1, %2, 0x7632;" : "=r"(r) : "r"(a), "r"(b));
    return r;
}

__device__ __forceinline__ uint32_t cvt_bf16x2(float hi_f, float lo_f) {
    uint32_t r;  // r[15:0]=bf16(lo_f), r[31:16]=bf16(hi_f)
    asm("cvt.rn.bf16x2.f32 %0, %1, %2;" : "=r"(r) : "f"(hi_f), "f"(lo_f));
    return r;
}

// truncation split of two fp32 into packed bf16x2 hi (exact) + lo (residual)
__device__ __forceinline__ void split_pack(float v0, float v1,
                                           uint32_t& hi, uint32_t& lo) {
    uint32_t u0 = __float_as_uint(v0), u1 = __float_as_uint(v1);
    hi = prmt_hi(u0, u1);
    float t0 = __uint_as_float(u0 & 0xFFFF0000u);
    float t1 = __uint_as_float(u1 & 0xFFFF0000u);
    lo = cvt_bf16x2(v1 - t1, v0 - t0);
}

#define CP_ASYNC16(dst_u32, src_ptr) \
    asm volatile("cp.async.cg.shared.global [%0], [%1], 16;" \
        :: "r"(dst_u32), "l"(src_ptr) : "memory")
#define CP_COMMIT() asm volatile("cp.async.commit_group;" ::: "memory")
#define CP_WAIT0() asm volatile("cp.async.wait_group 0;" ::: "memory")
#define CP_WAIT1() asm volatile("cp.async.wait_group 1;" ::: "memory")
#define CP_WAIT2() asm volatile("cp.async.wait_group 2;" ::: "memory")

// ============================================================================
// prep: split x and the 4 weight matrices into bf16 hi/lo (once per call)
// 2097152 float4 total: [0,1048576) = x, then 4 x 262144 per weight.
// ============================================================================
__global__ __launch_bounds__(256)
void prep_split_kernel(const float* __restrict__ x,
                       const float* __restrict__ wq, const float* __restrict__ wk,
                       const float* __restrict__ wv, const float* __restrict__ wo)
{
    const size_t i = (size_t)blockIdx.x * 256 + threadIdx.x;
    const float* src;
    char* dh;
    char* dl;
    size_t off;
    if (i < 1048576) {
        src = x; dh = (char*)g_xh; dl = (char*)g_xl; off = i;
    } else {
        const size_t j = i - 1048576;
        const int w = (int)(j >> 18);
        off = j & 262143;
        src = (w == 0) ? wq : (w == 1) ? wk : (w == 2) ? wv : wo;
        dh = (char*)g_wh + (size_t)w * 2097152;   // 1M elems * 2B per slab
        dl = (char*)g_wl + (size_t)w * 2097152;
    }
    float4 f = ((const float4*)src)[off];
    uint32_t h01, l01, h23, l23;
    split_pack(f.x, f.y, h01, l01);
    split_pack(f.z, f.w, h23, l23);
    *(uint2*)(dh + off * 8) = make_uint2(h01, h23);
    *(uint2*)(dl + off * 8) = make_uint2(l01, l23);
}

// ============================================================================
// GEMM (NT): C[m,n] = sum_k A[m,k]*W[n,k] + bias[n], inputs pre-split bf16.
// CTA tile 128x128, 8 warps of 64x32, K-chunk 32, 3-stage cp.async pipeline.
// D += Ah*Bh + Ah*Bl + Al*Bh (fp32 accum). Compute path identical to R10.
// ============================================================================
#define KC 32
#define NCH (Dn / KC)         // 32
#define RSTRIDE 80
#define MATB (128 * RSTRIDE)  // 10240
#define STAGE_B (4 * MATB)    // 40960
#define GEMM_SMEM (3 * STAGE_B) // 122880

// issue one chunk (Ah|Al|Bh|Bl slices) into stage st; 8 cp.async per thread
__device__ __forceinline__ void gemm_issue(uint32_t smem_u, int st, int tid,
                                           const char* const srcp[4],
                                           const int rowbase[4], int k0)
{
    const uint32_t sb = smem_u + (uint32_t)st * STAGE_B;
#pragma unroll
    for (int p = 0; p < 8; p++) {
        const int mat = p >> 1;
        const int j   = ((p & 1) << 8) + tid;     // 0..511
        const int row = j >> 2;
        const int c   = j & 3;
        const char* src = srcp[mat] +
            ((size_t)(rowbase[mat] + row) * Dn + k0 + c * 8) * 2;
        const uint32_t dst = sb + (uint32_t)(mat * MATB + row * RSTRIDE + c * 16);
        CP_ASYNC16(dst, src);
    }
}

template <bool SPLIT_OUT>
__device__ __forceinline__ void gemm_mma_body(
    const __nv_bfloat16* __restrict__ Ah, const __nv_bfloat16* __restrict__ Al,
    const __nv_bfloat16* __restrict__ Bh, const __nv_bfloat16* __restrict__ Bl,
    const float* __restrict__ bias,
    char* Ch, char* Cl, float* Cf)
{
    extern __shared__ char smem[];
    const uint32_t smem_u = smem_to_u32(smem);
    const int tid  = threadIdx.x;
    const int wid  = tid >> 5;
    const int lane = tid & 31;
    const int cCol = blockIdx.x;
    const int cRow = blockIdx.y;
    const int wr = wid >> 2;
    const int wc = wid & 3;

    const char* srcp[4] = {(const char*)Ah, (const char*)Al,
                           (const char*)Bh, (const char*)Bl};
    const int rowbase[4] = {cRow * 128, cRow * 128, cCol * 128, cCol * 128};

    float acc[16][4];
#pragma unroll
    for (int t = 0; t < 16; t++)
#pragma unroll
        for (int j = 0; j < 4; j++) acc[t][j] = 0.f;

    // prologue: chunks 0..2 into stages 0..2
#pragma unroll
    for (int s = 0; s < 3; s++) {
        gemm_issue(smem_u, s, tid, srcp, rowbase, s * KC);
        CP_COMMIT();
    }

    const int lr16 = lane & 15;
    const int lc16 = (lane & 16) ? 16 : 0;

    for (int i = 0; i < NCH; i++) {
        if (i < 30)       { CP_WAIT2(); }
        else if (i == 30) { CP_WAIT1(); }
        else              { CP_WAIT0(); }
        __syncthreads();

        const uint32_t base = smem_u + (uint32_t)(i % 3) * STAGE_B;
#pragma unroll
        for (int ks = 0; ks < 2; ks++) {
            const int cb = ks * 32 + lc16;
            uint32_t ah[4][4], al[4][4], bh[2][4], bl[2][4];
#pragma unroll
            for (int mt = 0; mt < 4; mt++) {
                const uint32_t ad = base +
                    (uint32_t)((wr * 64 + mt * 16 + lr16) * RSTRIDE + cb);
                ldsm_x4(ah[mt], ad);
                ldsm_x4(al[mt], ad + MATB);
            }
#pragma unroll
            for (int np = 0; np < 2; np++) {
                const uint32_t bd = base + 2 * MATB +
                    (uint32_t)((wc * 32 + np * 16 + lr16) * RSTRIDE + cb);
                ldsm_x4(bh[np], bd);
                ldsm_x4(bl[np], bd + MATB);
            }
#pragma unroll
            for (int mt = 0; mt < 4; mt++) {
#pragma unroll
                for (int nt = 0; nt < 4; nt++) {
                    const int np = nt >> 1, hf = nt & 1;
                    float* c = acc[mt * 4 + nt];
                    mma16816(c, ah[mt], bh[np][hf], bh[np][hf + 2]);
                    mma16816(c, ah[mt], bl[np][hf], bl[np][hf + 2]);
                    mma16816(c, al[mt], bh[np][hf], bh[np][hf + 2]);
                }
            }
        }
        __syncthreads();   // all warps done reading stage i%3

        if (i + 3 < NCH) {
            gemm_issue(smem_u, i % 3, tid, srcp, rowbase, (i + 3) * KC);
            CP_COMMIT();
        }
    }

    // epilogue
    const int r0 = lane >> 2;
    const int c0 = (lane & 3) * 2;
#pragma unroll
    for (int mt = 0; mt < 4; mt++) {
#pragma unroll
        for (int nt = 0; nt < 4; nt++) {
            const float* c = acc[mt * 4 + nt];
            const int grow = cRow * 128 + wr * 64 + mt * 16 + r0;
            const int gcol = cCol * 128 + wc * 32 + nt * 8 + c0;
            const float b0 = bias[gcol], b1 = bias[gcol + 1];
            const float v0 = c[0] + b0, v1 = c[1] + b1;
            const float v2 = c[2] + b0, v3 = c[3] + b1;
            if (SPLIT_OUT) {
                uint32_t hi, lo;
                const size_t off0 = ((size_t)grow * Dn + gcol) * 2;
                split_pack(v0, v1, hi, lo);
                *(uint32_t*)(Ch + off0) = hi;
                *(uint32_t*)(Cl + off0) = lo;
                const size_t off1 = ((size_t)(grow + 8) * Dn + gcol) * 2;
                split_pack(v2, v3, hi, lo);
                *(uint32_t*)(Ch + off1) = hi;
                *(uint32_t*)(Cl + off1) = lo;
            } else {
                *(float2*)(Cf + (size_t)grow * Dn + gcol) = make_float2(v0, v1);
                *(float2*)(Cf + (size_t)(grow + 8) * Dn + gcol) = make_float2(v2, v3);
            }
        }
    }
}

__global__ __launch_bounds__(256, 1)
void gemm_qkv_mma_kernel(const float* __restrict__ bq,
                         const float* __restrict__ bk,
                         const float* __restrict__ bv)
{
    const int z = blockIdx.z;
    const __nv_bfloat16* Bh = g_wh + (size_t)z * Dn * Dn;
    const __nv_bfloat16* Bl = g_wl + (size_t)z * Dn * Dn;
    const float* bias = (z == 0) ? bq : (z == 1) ? bk : bv;
    char* Ch = (char*)((z == 0) ? g_qh : (z == 1) ? g_kh : g_vh);
    char* Cl = (char*)((z == 0) ? g_ql : (z == 1) ? g_kl : g_vl);
    gemm_mma_body<true>(g_xh, g_xl, Bh, Bl, bias, Ch, Cl, nullptr);
}

__global__ __launch_bounds__(256, 1)
void gemm_out_mma_kernel(const float* __restrict__ bout, float* __restrict__ out)
{
    gemm_mma_body<false>(g_oh, g_ol, g_wh + (size_t)3 * Dn * Dn,
                         g_wl + (size_t)3 * Dn * Dn, bout,
                         nullptr, nullptr, out);
}

// ============================================================================
// Tensor-core causal flash attention. Inputs pre-split bf16 (no conversion in
// the loop). K/V tiles double-buffered via cp.async. Compute identical to R10.
// Writes O as split bf16 for the out-projection.
// ============================================================================
#define ARST 144
#define AQL_OFF 9216                     // Q lo offset from Q hi
#define AKV_BASE 18432                   // first KV stage
#define AKV_STAGE 36864                  // 4 mats x 9216
#define ATT_SMEM (AKV_BASE + 2 * AKV_STAGE)   // 92160

__device__ __forceinline__ void att_issue_kv(uint32_t smem_u, int st, int tid,
                                             int b, int h, int kt)
{
    const char* srcs[4] = {(const char*)g_kh, (const char*)g_kl,
                           (const char*)g_vh, (const char*)g_vl};
    const uint32_t base = smem_u + AKV_BASE + (uint32_t)st * AKV_STAGE;
#pragma unroll
    for (int p = 0; p < 16; p++) {
        const int idx = p * 128 + tid;
        const int mat = idx >> 9;
        const int j   = idx & 511;
        const int row = j >> 3;
        const int c   = j & 7;
        const char* src = srcs[mat] +
            ((size_t)(b * Sn + kt * 64 + row) * Dn + h * HDn + c * 8) * 2;
        const uint32_t dst = base + (uint32_t)(mat * 9216 + row * ARST + c * 16);
        CP_ASYNC16(dst, src);
    }
}

__global__ __launch_bounds__(128)
void flash_attn_mma_kernel()
{
    extern __shared__ char smem[];
    const uint32_t smem_u = smem_to_u32(smem);
    const int tid  = threadIdx.x;
    const int wid  = tid >> 5;
    const int lane = tid & 31;
    const int qt = gridDim.x - 1 - blockIdx.x;   // heavy tiles first
    const int h  = blockIdx.y;
    const int b  = blockIdx.z;

    const int lr16 = lane & 15;
    const int lc16 = (lane & 16) ? 16 : 0;
    const int rbase = wid * 16 + (lane >> 2);
    const int cquad = (lane & 3) * 2;

    // issue Q (hi+lo) + KV tile 0 as the first commit group
    {
        const char* qs[2] = {(const char*)g_qh, (const char*)g_ql};
#pragma unroll
        for (int p = 0; p < 8; p++) {
            const int idx = p * 128 + tid;
            const int mat = idx >> 9;
            const int j   = idx & 511;
            const int row = j >> 3;
            const int c   = j & 7;
            const char* src = qs[mat] +
                ((size_t)(b * Sn + qt * 64 + row) * Dn + h * HDn + c * 8) * 2;
            const uint32_t dst = smem_u +
                (uint32_t)(mat * AQL_OFF + row * ARST + c * 16);
            CP_ASYNC16(dst, src);
        }
        att_issue_kv(smem_u, 0, tid, b, h, 0);
        CP_COMMIT();
    }

    uint32_t qh[4][4], ql[4][4];
    bool qloaded = false;

    float s[8][4];
    float o[8][4];
#pragma unroll
    for (int f = 0; f < 8; f++)
#pragma unroll
        for (int j = 0; j < 4; j++) o[f][j] = 0.f;
    float m0 = -1e30f, m1 = -1e30f, l0 = 0.f, l1 = 0.f;

    for (int kt = 0; kt <= qt; kt++) {
        if (kt < qt) {
            att_issue_kv(smem_u, (kt + 1) & 1, tid, b, h, kt + 1);
            CP_COMMIT();
            CP_WAIT1();
        } else {
            CP_WAIT0();
        }
        __syncthreads();

        if (!qloaded) {
            qloaded = true;
#pragma unroll
            for (int kc = 0; kc < 4; kc++) {
                const uint32_t ad = smem_u +
                    (uint32_t)((wid * 16 + lr16) * ARST + kc * 32 + lc16);
                ldsm_x4(qh[kc], ad);
                ldsm_x4(ql[kc], ad + AQL_OFF);
            }
        }

        const uint32_t kbase = smem_u + AKV_BASE + (uint32_t)(kt & 1) * AKV_STAGE;
        const uint32_t vbase = kbase + 2 * 9216;

        const bool diag = (kt == qt);
        const int  npb   = diag ? wid : 3;
        const int  nfrag = (npb + 1) * 2;

        // ---- S = Q K^T ----
#pragma unroll
        for (int nt = 0; nt < 8; nt++) {
            if (nt >= nfrag) continue;
#pragma unroll
            for (int j = 0; j < 4; j++) s[nt][j] = 0.f;
        }
        for (int np = 0; np <= npb; np++) {
            uint32_t kbh[4][4], kbl[4][4];
#pragma unroll
            for (int kc = 0; kc < 4; kc++) {
                const uint32_t ad = kbase +
                    (uint32_t)((np * 16 + lr16) * ARST + kc * 32 + lc16);
                ldsm_x4(kbh[kc], ad);
                ldsm_x4(kbl[kc], ad + 9216);
            }
#pragma unroll
            for (int kc = 0; kc < 4; kc++) {
#pragma unroll
                for (int hf = 0; hf < 2; hf++) {
                    float* c = s[np * 2 + hf];
                    mma16816(c, qh[kc], kbh[kc][hf], kbh[kc][hf + 2]);
                    mma16816(c, qh[kc], kbl[kc][hf], kbl[kc][hf + 2]);
                    mma16816(c, ql[kc], kbh[kc][hf], kbh[kc][hf + 2]);
                }
            }
        }

        // ---- online softmax (rows rbase, rbase+8) ----
        float mt0 = -1e30f, mt1 = -1e30f;
#pragma unroll
        for (int nt = 0; nt < 8; nt++) {
            if (nt >= nfrag) continue;
#pragma unroll
            for (int j = 0; j < 4; j++) {
                float v = s[nt][j] * 0.125f;
                if (diag) {
                    const int col = nt * 8 + cquad + (j & 1);
                    const int r   = rbase + ((j >> 1) << 3);
                    if (col > r) v = -1e30f;
                }
                s[nt][j] = v;
            }
            mt0 = fmaxf(mt0, fmaxf(s[nt][0], s[nt][1]));
            mt1 = fmaxf(mt1, fmaxf(s[nt][2], s[nt][3]));
        }
        mt0 = fmaxf(mt0, __shfl_xor_sync(0xffffffffu, mt0, 1));
        mt0 = fmaxf(mt0, __shfl_xor_sync(0xffffffffu, mt0, 2));
        mt1 = fmaxf(mt1, __shfl_xor_sync(0xffffffffu, mt1, 1));
        mt1 = fmaxf(mt1, __shfl_xor_sync(0xffffffffu, mt1, 2));

        const float mn0 = fmaxf(m0, mt0), mn1 = fmaxf(m1, mt1);
        const float corr0 = __expf(m0 - mn0), corr1 = __expf(m1 - mn1);
        m0 = mn0; m1 = mn1;

        float ls0 = 0.f, ls1 = 0.f;
#pragma unroll
        for (int nt = 0; nt < 8; nt++) {
            if (nt >= nfrag) continue;
            const float p0 = __expf(s[nt][0] - m0);
            const float p1 = __expf(s[nt][1] - m0);
            const float p2 = __expf(s[nt][2] - m1);
            const float p3 = __expf(s[nt][3] - m1);
            ls0 += p0 + p1; ls1 += p2 + p3;
            s[nt][0] = p0; s[nt][1] = p1; s[nt][2] = p2; s[nt][3] = p3;
        }
        ls0 += __shfl_xor_sync(0xffffffffu, ls0, 1);
        ls0 += __shfl_xor_sync(0xffffffffu, ls0, 2);
        ls1 += __shfl_xor_sync(0xffffffffu, ls1, 1);
        ls1 += __shfl_xor_sync(0xffffffffu, ls1, 2);
        l0 = l0 * corr0 + ls0;
        l1 = l1 * corr1 + ls1;

#pragma unroll
        for (int f = 0; f < 8; f++) {
            o[f][0] *= corr0; o[f][1] *= corr0;
            o[f][2] *= corr1; o[f][3] *= corr1;
        }

        // ---- pack P into A-fragments ----
        uint32_t pfh[4][4], pfl[4][4];
#pragma unroll
        for (int g = 0; g < 4; g++) {
            if (g > npb) continue;
            split_pack(s[2 * g][0],     s[2 * g][1],     pfh[g][0], pfl[g][0]);
            split_pack(s[2 * g][2],     s[2 * g][3],     pfh[g][1], pfl[g][1]);
            split_pack(s[2 * g + 1][0], s[2 * g + 1][1], pfh[g][2], pfl[g][2]);
            split_pack(s[2 * g + 1][2], s[2 * g + 1][3], pfh[g][3], pfl[g][3]);
        }

        // ---- O += P V ----
        const int vrow_off = ((lane >> 4) << 3) + (lane & 7);
        const int vcol_off = ((lane >> 3) & 1) * 16;
#pragma unroll
        for (int kc = 0; kc < 4; kc++) {
            if (kc > npb) continue;
            uint32_t vbh[4][4], vbl[4][4];
#pragma unroll
            for (int dg = 0; dg < 4; dg++) {
                const uint32_t ad = vbase +
                    (uint32_t)((kc * 16 + vrow_off) * ARST + dg * 32 + vcol_off);
                ldsm_x4_t(vbh[dg], ad);
                ldsm_x4_t(vbl[dg], ad + 9216);
            }
#pragma unroll
            for (int dg = 0; dg < 4; dg++) {
#pragma unroll
                for (int hf = 0; hf < 2; hf++) {
                    float* c = o[dg * 2 + hf];
                    mma16816(c, pfh[kc], vbh[dg][hf], vbh[dg][hf + 2]);
                    mma16816(c, pfh[kc], vbl[dg][hf], vbl[dg][hf + 2]);
                    mma16816(c, pfl[kc], vbh[dg][hf], vbh[dg][hf + 2]);
                }
            }
        }
        __syncthreads();   // all warps done reading buf kt&1 before reuse
    }

    // ---- epilogue: normalize, split, store bf16 hi/lo ----
    const float inv0 = 1.f / l0, inv1 = 1.f / l1;
    const int rlo = wid * 16 + (lane >> 2);
#pragma unroll
    for (int f = 0; f < 8; f++) {
        const int col = f * 8 + cquad;
        uint32_t hi, lo;
        const size_t off0 =
            ((size_t)(b * Sn + qt * 64 + rlo) * Dn + h * HDn + col) * 2;
        split_pack(o[f][0] * inv0, o[f][1] * inv0, hi, lo);
        *(uint32_t*)((char*)g_oh + off0) = hi;
        *(uint32_t*)((char*)g_ol + off0) = lo;
        const size_t off1 =
            ((size_t)(b * Sn + qt * 64 + rlo + 8) * Dn + h * HDn + col) * 2;
        split_pack(o[f][2] * inv1, o[f][3] * inv1, hi, lo);
        *(uint32_t*)((char*)g_oh + off1) = hi;
        *(uint32_t*)((char*)g_ol + off1) = lo;
    }
}

// ============================================================================
// launch
// ============================================================================
extern "C" void kernel_launch(void* const* d_in, const int* in_sizes, int n_in,
                              void* d_out, int out_size)
{
    const float* x    = (const float*)d_in[0];
    const float* w_q  = (const float*)d_in[1];
    const float* b_q  = (const float*)d_in[2];
    const float* w_k  = (const float*)d_in[3];
    const float* b_k  = (const float*)d_in[4];
    const float* w_v  = (const float*)d_in[5];
    const float* b_v  = (const float*)d_in[6];
    const float* w_o  = (const float*)d_in[7];
    const float* b_o  = (const float*)d_in[8];
    float* out = (float*)d_out;

    cudaFuncSetAttribute(gemm_qkv_mma_kernel,
                         cudaFuncAttributeMaxDynamicSharedMemorySize, GEMM_SMEM);
    cudaFuncSetAttribute(gemm_out_mma_kernel,
                         cudaFuncAttributeMaxDynamicSharedMemorySize, GEMM_SMEM);
    cudaFuncSetAttribute(flash_attn_mma_kernel,
                         cudaFuncAttributeMaxDynamicSharedMemorySize, ATT_SMEM);

    // 0. pre-split x and weights into bf16 hi/lo
    prep_split_kernel<<<8192, 256>>>(x, w_q, w_k, w_v, w_o);

    // 1. Q, K, V projections (split-bf16 in AND out)
    {
        dim3 grid(Dn / 128, Mn / 128, 3);
        gemm_qkv_mma_kernel<<<grid, 256, GEMM_SMEM>>>(b_q, b_k, b_v);
    }

    // 2. causal flash attention (tensor cores, cp.async pipelined)
    {
        dim3 grid(Sn / 64, Hn, Bn);
        flash_attn_mma_kernel<<<grid, 128, ATT_SMEM>>>();
    }

    // 3. output projection (fp32 out)
    {
        dim3 grid(Dn / 128, Mn / 128, 1);
        gemm_out_mma_kernel<<<grid, 256, GEMM_SMEM>>>(b_o, out);
    }
}